// round 1
// baseline (speedup 1.0000x reference)
#include <cuda_runtime.h>

// Equivariant linear: y[b,v,i] = c * sum_u W[v,u] * x[b,u,i], per irrep block.
// Irreps: (mul, d) in {(256,1),(128,3),(64,5),(32,7)}; FEAT = 1184; B = 131072.
// Each block is a GEMM with M' = B*d rows (row r = b*d + i), N = K = mul.

#define FEAT 1184
#define BATCH 131072

template<int MUL, int D, int BN, int BK, int TM, int TN, int NT>
__global__ __launch_bounds__(NT) void eqlin_kernel(
    const float* __restrict__ x, const float* __restrict__ w,
    float* __restrict__ out, int xo, int wo, float c)
{
    constexpr int BM = 128;
    // upper bound on distinct batch rows touched by one BM-row tile
    constexpr int NBL = (BM + D - 1) / D + 1;

    __shared__ float As[BK][BM];        // A tile, k-major rows (512B rows, 16B aligned)
    __shared__ float Ws[BK][BN + 4];    // W tile (transposed, pre-scaled), +4 pad keeps 16B row align

    const int tid = threadIdx.x;
    constexpr int NTX = BN / TN;
    const int tx = tid % NTX;
    const int ty = tid / NTX;
    const int r0 = blockIdx.x * BM;     // row offset into M' = B*D
    const int v0 = blockIdx.y * BN;     // output-channel offset

    float acc[TM][TN];
#pragma unroll
    for (int m = 0; m < TM; m++)
#pragma unroll
        for (int n = 0; n < TN; n++) acc[m][n] = 0.0f;

    const int b_lo = r0 / D;

    for (int k0 = 0; k0 < MUL; k0 += BK) {
        // ---- Load A tile: for each batch row b in range, the needed elements
        //      (u in [k0,k0+BK), all i) are one CONTIGUOUS chunk of BK*D floats
        //      at x[b*FEAT + xo + k0*D]. Consecutive threads -> consecutive floats.
#pragma unroll
        for (int e = tid; e < NBL * BK * D; e += NT) {
            int bl = e / (BK * D);
            int cc = e % (BK * D);          // = u_local*D + i
            int b  = b_lo + bl;
            if (b < BATCH) {
                float val = x[b * FEAT + xo + k0 * D + cc];
                int r  = b * D + (cc % D) - r0;   // row within tile
                int kk = cc / D;
                if (r >= 0 && r < BM) As[kk][r] = val;
            }
        }
        // ---- Load W tile transposed + pre-scaled: consecutive threads walk k
        //      (contiguous in global), store Ws[kk][v].
#pragma unroll
        for (int e = tid; e < BN * BK; e += NT) {
            int kk = e % BK;
            int v  = e / BK;
            Ws[kk][v] = c * w[wo + (v0 + v) * MUL + (k0 + kk)];
        }
        __syncthreads();

#pragma unroll
        for (int k = 0; k < BK; k++) {
            float a[TM], bb[TN];
#pragma unroll
            for (int m = 0; m < TM; m++) a[m] = As[k][ty * TM + m];
#pragma unroll
            for (int n = 0; n < TN; n++) bb[n] = Ws[k][tx * TN + n];
#pragma unroll
            for (int m = 0; m < TM; m++)
#pragma unroll
                for (int n = 0; n < TN; n++)
                    acc[m][n] = fmaf(a[m], bb[n], acc[m][n]);
        }
        __syncthreads();
    }

    // ---- Write back: out[b*FEAT + xo + v*D + i]
#pragma unroll
    for (int m = 0; m < TM; m++) {
        int rr = r0 + ty * TM + m;
        int b = rr / D, i = rr % D;
        float* o = out + b * FEAT + xo + i;
#pragma unroll
        for (int n = 0; n < TN; n++)
            o[(v0 + tx * TN + n) * D] = acc[m][n];
    }
}

extern "C" void kernel_launch(void* const* d_in, const int* in_sizes, int n_in,
                              void* d_out, int out_size)
{
    const float* x = (const float*)d_in[0];
    const float* w = (const float*)d_in[1];
    float* out = (float*)d_out;

    // block 0: mul=256, d=1, xo=0,   wo=0,     c = 1/sqrt(256)
    // M' = 131072 -> 1024 m-tiles, N = 256 -> 2 n-tiles of 128
    eqlin_kernel<256, 1, 128, 16, 8, 8, 256>
        <<<dim3(131072 / 128, 2), 256>>>(x, w, out, 0, 0, 0.0625f);

    // block 1: mul=128, d=3, xo=256, wo=65536, c = 1/sqrt(128)
    // M' = 393216 -> 3072 m-tiles, N = 128 -> 1 n-tile
    eqlin_kernel<128, 3, 128, 16, 8, 8, 256>
        <<<dim3(393216 / 128, 1), 256>>>(x, w, out, 256, 65536, 0.08838834764831843f);

    // block 2: mul=64, d=5, xo=640, wo=81920, c = 1/sqrt(64)
    // M' = 655360 -> 5120 m-tiles, N = 64
    eqlin_kernel<64, 5, 64, 16, 8, 8, 128>
        <<<dim3(655360 / 128, 1), 128>>>(x, w, out, 640, 81920, 0.125f);

    // block 3: mul=32, d=7, xo=960, wo=86016, c = 1/sqrt(32)
    // M' = 917504 -> 7168 m-tiles, N = 32
    eqlin_kernel<32, 7, 32, 16, 8, 4, 128>
        <<<dim3(917504 / 128, 1), 128>>>(x, w, out, 960, 86016, 0.17677669529663687f);
}

// round 3
// speedup vs baseline: 2.3002x; 2.3002x over previous
#include <cuda_runtime.h>
#include <cuda_bf16.h>
#include <cstdint>

#define FEAT 1184

// Pre-split weights (scaled by c): hi/lo bf16 decomposition of c*W.
__device__ __align__(16) __nv_bfloat16 g_whi[87040];
__device__ __align__(16) __nv_bfloat16 g_wlo[87040];

__global__ void prep_w(const float* __restrict__ w) {
    int i = blockIdx.x * 256 + threadIdx.x;
    if (i >= 87040) return;
    float c = (i < 65536) ? 0.0625f
            : (i < 81920) ? 0.08838834764831843f
            : (i < 86016) ? 0.125f
            : 0.17677669529663687f;
    float v = w[i] * c;
    __nv_bfloat16 h = __float2bfloat16_rn(v);
    g_whi[i] = h;
    g_wlo[i] = __float2bfloat16_rn(v - __bfloat162float(h));
}

static __device__ __forceinline__ uint32_t s2u(const void* p) {
    return (uint32_t)__cvta_generic_to_shared(p);
}
static __device__ __forceinline__ uint32_t sw128(uint32_t off) {
    return off ^ ((off >> 3) & 0x70);
}
// pack2(a, b): low half = bf16(a), high half = bf16(b)
static __device__ __forceinline__ uint32_t pack2(float a, float b) {
    uint32_t r;
    asm("cvt.rn.bf16x2.f32 %0, %1, %2;" : "=r"(r) : "f"(b), "f"(a));
    return r;
}
static __device__ __forceinline__ void ldsm4(uint32_t* r, uint32_t addr) {
    asm volatile("ldmatrix.sync.aligned.m8n8.x4.shared.b16 {%0,%1,%2,%3}, [%4];"
                 : "=r"(r[0]), "=r"(r[1]), "=r"(r[2]), "=r"(r[3]) : "r"(addr));
}
static __device__ __forceinline__ void mma16816(float* c, const uint32_t* a,
                                                const uint32_t* b) {
    asm volatile("mma.sync.aligned.m16n8k16.row.col.f32.bf16.bf16.f32 "
                 "{%0,%1,%2,%3}, {%4,%5,%6,%7}, {%8,%9}, {%0,%1,%2,%3};"
                 : "+f"(c[0]), "+f"(c[1]), "+f"(c[2]), "+f"(c[3])
                 : "r"(a[0]), "r"(a[1]), "r"(a[2]), "r"(a[3]),
                   "r"(b[0]), "r"(b[1]));
}

// GEMM per irrep block: y[r, v] = sum_k A[r,k] * (c*W[v,k]),
//   r = b*D + i,  A[r,k] = x[b*FEAT + xo + k*D + i]
template<int MUL, int D, int BN>
__global__ void __launch_bounds__(256, 1) eqlin_mma(
    const float* __restrict__ x, float* __restrict__ out,
    int xo, int wo, int mtiles)
{
    constexpr int KC     = (MUL < 64) ? MUL : 64;
    constexpr int NCH    = MUL / KC;
    constexpr int KSTEPS = KC / 16;
    constexpr int OCTS   = KC / 8;
    constexpr int TASKS  = (128 * OCTS) / 256;
    constexpr int WSZ    = NCH * BN * 128;       // bytes per W precision
    constexpr int W_HI   = 0;
    constexpr int W_LO   = WSZ;
    constexpr int A0     = 2 * WSZ;              // 2 bufs x (hi 16KB + lo 16KB)
    constexpr int WN     = BN / 2;               // per-warp N extent
    constexpr int NT8    = WN / 8;               // n8 tiles per warp

    extern __shared__ char smem[];
    const uint32_t sb = s2u(smem);
    const int tid  = threadIdx.x;
    const int lane = tid & 31;
    const int warp = tid >> 5;
    const int wm   = warp >> 1;
    const int wn   = warp & 1;
    const int v0   = blockIdx.y * BN;

    // ---- Resident W (hi + lo), chunk-major rows of 128B, SW128 ----
    for (int e = tid; e < BN * (MUL / 8); e += 256) {
        int v = e / (MUL / 8), o = e % (MUL / 8);
        int k = o * 8;
        uint4 hv = *(const uint4*)(g_whi + wo + (size_t)(v0 + v) * MUL + k);
        uint4 lv = *(const uint4*)(g_wlo + wo + (size_t)(v0 + v) * MUL + k);
        uint32_t off = (uint32_t)((k / KC) * (BN * 128) + v * 128 + (k % KC) * 2);
        uint32_t sw  = sw128(off);
        *(uint4*)(smem + W_HI + sw) = hv;
        *(uint4*)(smem + W_LO + sw) = lv;
    }

    float acc[2][NT8][4];
    float st[TASKS][8];

    auto ldg_chunk = [&](int m, int c) {
#pragma unroll
        for (int t = 0; t < TASKS; t++) {
            int e = tid + t * 256;
            int rl = e & 127, o = e >> 7;
            int r = m * 128 + rl;
            int b = r / D, i = r - b * D;
            const float* xp = x + (size_t)b * FEAT + xo + (c * KC + o * 8) * D + i;
            if (D == 1) {
                float4 q0 = *(const float4*)xp;
                float4 q1 = *(const float4*)(xp + 4);
                st[t][0] = q0.x; st[t][1] = q0.y; st[t][2] = q0.z; st[t][3] = q0.w;
                st[t][4] = q1.x; st[t][5] = q1.y; st[t][6] = q1.z; st[t][7] = q1.w;
            } else {
#pragma unroll
                for (int j = 0; j < 8; j++) st[t][j] = __ldg(xp + j * D);
            }
        }
    };

    auto sts_chunk = [&](int buf) {
        const int ah = A0 + buf * 32768;
        const int al = ah + 16384;
#pragma unroll
        for (int t = 0; t < TASKS; t++) {
            int e = tid + t * 256;
            int rl = e & 127, o = e >> 7;
            uint32_t hh[4], ll[4];
#pragma unroll
            for (int p = 0; p < 4; p++) {
                float a = st[t][2 * p], b = st[t][2 * p + 1];
                uint32_t h = pack2(a, b);
                float ra = a - __uint_as_float(h << 16);
                float rb = b - __uint_as_float(h & 0xFFFF0000u);
                hh[p] = h;
                ll[p] = pack2(ra, rb);
            }
            uint32_t sw = sw128((uint32_t)(rl * 128 + o * 16));
            *(uint4*)(smem + ah + sw) = make_uint4(hh[0], hh[1], hh[2], hh[3]);
            *(uint4*)(smem + al + sw) = make_uint4(ll[0], ll[1], ll[2], ll[3]);
        }
    };

    auto mma_chunk = [&](int buf, int c) {
        const int ah = A0 + buf * 32768;
        const int al = ah + 16384;
        const int q = lane >> 3, p = lane & 7;
#pragma unroll
        for (int s = 0; s < KSTEPS; s++) {
            uint32_t afh[2][4], afl[2][4];
#pragma unroll
            for (int mt = 0; mt < 2; mt++) {
                uint32_t row = (uint32_t)(wm * 32 + mt * 16 + (q & 1) * 8 + p);
                uint32_t kb  = (uint32_t)(s * 32 + (q >> 1) * 16);
                uint32_t sw  = sw128(row * 128 + kb);
                ldsm4(afh[mt], sb + ah + sw);
                ldsm4(afl[mt], sb + al + sw);
            }
#pragma unroll
            for (int ntp = 0; ntp < NT8 / 2; ntp++) {
                uint32_t vv = (uint32_t)(wn * WN + ntp * 16 + (q >> 1) * 8 + p);
                uint32_t kb = (uint32_t)(s * 32 + (q & 1) * 16);
                uint32_t off = (uint32_t)(c * (BN * 128)) + sw128(vv * 128 + kb);
                uint32_t bh[4], bl[4];
                ldsm4(bh, sb + W_HI + off);
                ldsm4(bl, sb + W_LO + off);
#pragma unroll
                for (int t2 = 0; t2 < 2; t2++) {
                    int nt = ntp * 2 + t2;
#pragma unroll
                    for (int mt = 0; mt < 2; mt++) {
                        mma16816(acc[mt][nt], afh[mt], bh + 2 * t2);
                        mma16816(acc[mt][nt], afh[mt], bl + 2 * t2);
                        mma16816(acc[mt][nt], afl[mt], bh + 2 * t2);
                    }
                }
            }
        }
    };

    int g = 0;
    ldg_chunk(blockIdx.x, 0);

    for (int m = blockIdx.x; m < mtiles; m += gridDim.x) {
#pragma unroll
        for (int mt = 0; mt < 2; mt++)
#pragma unroll
            for (int nt = 0; nt < NT8; nt++)
#pragma unroll
                for (int j = 0; j < 4; j++) acc[mt][nt][j] = 0.0f;

#pragma unroll 1
        for (int c = 0; c < NCH; c++) {
            int buf = g & 1;
            sts_chunk(buf);
            __syncthreads();
            int cn = c + 1, mn = m;
            if (cn == NCH) { cn = 0; mn = m + gridDim.x; }
            if (mn < mtiles) ldg_chunk(mn, cn);
            mma_chunk(buf, c);
            g++;
        }

        // ---- Epilogue: registers -> gmem ----
        const int row_base = m * 128 + wm * 32 + (lane >> 2);
        const int col_base = v0 + wn * WN + 2 * (lane & 3);
#pragma unroll
        for (int mt = 0; mt < 2; mt++) {
#pragma unroll
            for (int nt = 0; nt < NT8; nt++) {
                float* a = acc[mt][nt];
                int cc = col_base + nt * 8;
                int r1 = row_base + mt * 16;
                int r2 = r1 + 8;
                if (D == 1) {
                    *(float2*)(out + (size_t)r1 * FEAT + xo + cc) =
                        make_float2(a[0], a[1]);
                    *(float2*)(out + (size_t)r2 * FEAT + xo + cc) =
                        make_float2(a[2], a[3]);
                } else {
                    int b1 = r1 / D, i1 = r1 - b1 * D;
                    int b2 = r2 / D, i2 = r2 - b2 * D;
                    float* o1 = out + (size_t)b1 * FEAT + xo + i1;
                    float* o2 = out + (size_t)b2 * FEAT + xo + i2;
                    o1[(size_t)cc * D]       = a[0];
                    o1[(size_t)(cc + 1) * D] = a[1];
                    o2[(size_t)cc * D]       = a[2];
                    o2[(size_t)(cc + 1) * D] = a[3];
                }
            }
        }
    }
}

extern "C" void kernel_launch(void* const* d_in, const int* in_sizes, int n_in,
                              void* d_out, int out_size)
{
    const float* x = (const float*)d_in[0];
    const float* w = (const float*)d_in[1];
    float* out = (float*)d_out;

    prep_w<<<(87040 + 255) / 256, 256>>>(w);

    constexpr int SM0 = 2 * (4 * 128 * 128) + 65536;  // 196608
    constexpr int SM1 = 2 * (2 * 128 * 128) + 65536;  // 131072
    constexpr int SM2 = 2 * (1 * 64 * 128) + 65536;   // 81920
    constexpr int SM3 = 2 * (1 * 32 * 128) + 65536;   // 73728

    cudaFuncSetAttribute(eqlin_mma<256, 1, 128>, cudaFuncAttributeMaxDynamicSharedMemorySize, SM0);
    cudaFuncSetAttribute(eqlin_mma<128, 3, 128>, cudaFuncAttributeMaxDynamicSharedMemorySize, SM1);
    cudaFuncSetAttribute(eqlin_mma<64, 5, 64>,   cudaFuncAttributeMaxDynamicSharedMemorySize, SM2);
    cudaFuncSetAttribute(eqlin_mma<32, 7, 32>,   cudaFuncAttributeMaxDynamicSharedMemorySize, SM3);

    // block 0: mul=256, d=1: 1024 m-tiles, 2 n-tiles of 128
    eqlin_mma<256, 1, 128><<<dim3(74, 2), 256, SM0>>>(x, out, 0, 0, 1024);
    // block 1: mul=128, d=3: 3072 m-tiles
    eqlin_mma<128, 3, 128><<<dim3(148, 1), 256, SM1>>>(x, out, 256, 65536, 3072);
    // block 2: mul=64, d=5: 5120 m-tiles
    eqlin_mma<64, 5, 64><<<dim3(148, 1), 256, SM2>>>(x, out, 640, 81920, 5120);
    // block 3: mul=32, d=7: 7168 m-tiles
    eqlin_mma<32, 7, 32><<<dim3(148, 1), 256, SM3>>>(x, out, 960, 86016, 7168);
}

// round 5
// speedup vs baseline: 2.8103x; 1.2217x over previous
#include <cuda_runtime.h>
#include <cuda_fp16.h>
#include <cstdint>

#define FEAT 1184
#define BATCH 131072

// Pre-split weights (scaled by c): hi/lo fp16 decomposition of c*W.
__device__ __align__(16) __half g_whi[87040];
__device__ __align__(16) __half g_wlo[87040];

__global__ void prep_w(const float* __restrict__ w) {
    int i = blockIdx.x * 256 + threadIdx.x;
    if (i >= 87040) return;
    float c = (i < 65536) ? 0.0625f
            : (i < 81920) ? 0.08838834764831843f
            : (i < 86016) ? 0.125f
            : 0.17677669529663687f;
    float v = w[i] * c;
    __half h = __float2half_rn(v);
    g_whi[i] = h;
    g_wlo[i] = __float2half_rn(v - __half2float(h));
}

static __device__ __forceinline__ uint32_t s2u(const void* p) {
    return (uint32_t)__cvta_generic_to_shared(p);
}
static __device__ __forceinline__ uint32_t sw128(uint32_t off) {
    return off ^ ((off >> 3) & 0x70);
}
// pack two floats into f16x2: low half = a, high half = b
static __device__ __forceinline__ uint32_t packh2(float a, float b) {
    __half2 h = __floats2half2_rn(a, b);
    return *(uint32_t*)&h;
}
static __device__ __forceinline__ void ldsm4(uint32_t* r, uint32_t addr) {
    asm volatile("ldmatrix.sync.aligned.m8n8.x4.shared.b16 {%0,%1,%2,%3}, [%4];"
                 : "=r"(r[0]), "=r"(r[1]), "=r"(r[2]), "=r"(r[3]) : "r"(addr));
}
static __device__ __forceinline__ void mma16816(float* c, const uint32_t* a,
                                                const uint32_t* b) {
    asm volatile("mma.sync.aligned.m16n8k16.row.col.f32.f16.f16.f32 "
                 "{%0,%1,%2,%3}, {%4,%5,%6,%7}, {%8,%9}, {%0,%1,%2,%3};"
                 : "+f"(c[0]), "+f"(c[1]), "+f"(c[2]), "+f"(c[3])
                 : "r"(a[0]), "r"(a[1]), "r"(a[2]), "r"(a[3]),
                   "r"(b[0]), "r"(b[1]));
}

// GEMM per irrep block: y[r, v] = sum_k A[r,k] * (c*W[v,k]),
//   r = b*D + i,  A[r,k] = x[b*FEAT + xo + k*D + i]
template<int MUL, int D, int BN, int NT>
__global__ void __launch_bounds__(NT, (NT == 256) ? 2 : 1) eqlin(
    const float* __restrict__ x, float* __restrict__ out,
    int xo, int wo, int mtiles)
{
    constexpr int KC      = (MUL < 64) ? MUL : 64;
    constexpr int NCH     = MUL / KC;
    constexpr int KSTEPS  = KC / 16;
    constexpr int OCTS    = KC / 8;
    constexpr int WSZ     = NCH * BN * 128;       // bytes per W precision
    constexpr int A_OFF   = 2 * WSZ;
    constexpr int NABUF   = (D == 1) ? 2 : 1;
    constexpr int STG_OFF = A_OFF + NABUF * 16384;
    constexpr int NB      = 127 / D + 2;          // batches touched per tile
    constexpr int STRIDE  = KC * D + 4;           // floats; == 4 (mod 32), mult of 4
    constexpr int F4PB    = KC * D / 4;           // float4 per batch per chunk
    constexpr int WNW     = NT / 128;             // warps along N
    constexpr int WN      = BN / WNW;
    constexpr int NT8     = WN / 8;
    constexpr int TASKS   = (128 * OCTS) / NT;

    extern __shared__ char smem[];
    const uint32_t sb = s2u(smem);
    float* stgF = (float*)(smem + STG_OFF);
    const int tid  = threadIdx.x;
    const int lane = tid & 31;
    const int warp = tid >> 5;
    const int wm   = warp / WNW;
    const int wn   = warp % WNW;
    const int v0   = blockIdx.y * BN;

    // ---- Resident W (hi + lo fp16), chunk-major 128B rows, SW128 ----
    for (int e = tid; e < BN * (MUL / 8); e += NT) {
        int v = e / (MUL / 8), o = e % (MUL / 8);
        int k = o * 8;
        uint4 hv = *(const uint4*)(g_whi + wo + (size_t)(v0 + v) * MUL + k);
        uint4 lv = *(const uint4*)(g_wlo + wo + (size_t)(v0 + v) * MUL + k);
        uint32_t off = (uint32_t)((k / KC) * (BN * 128) + v * 128 + (k % KC) * 2);
        uint32_t sw  = sw128(off);
        *(uint4*)(smem + sw) = hv;
        *(uint4*)(smem + WSZ + sw) = lv;
    }

    float acc[2][NT8][4];
    float st[(D == 1) ? TASKS : 1][8];   // reg prefetch (D==1 path only)

    // cp.async staging load: contiguous float4s of the chunk's gmem span
    auto stage_ld = [&](int m, int c) {
        int b_lo = (m * 128) / D;
        for (int e = tid; e < NB * F4PB; e += NT) {
            int bl = e / F4PB, f = e - bl * F4PB;
            int b = b_lo + bl;
            if (b >= BATCH) b = BATCH - 1;
            const float* src = x + (size_t)b * FEAT + xo + c * (KC * D) + f * 4;
            uint32_t dst = sb + STG_OFF + (uint32_t)(bl * STRIDE + f * 4) * 4;
            asm volatile("cp.async.cg.shared.global [%0], [%1], 16;"
                         :: "r"(dst), "l"(src) : "memory");
        }
        asm volatile("cp.async.commit_group;" ::: "memory");
    };

    // D>1: strided LDS from staging -> fp16 -> swizzled A
    auto conv_chunk = [&](int m) {
        int b_lo = (m * 128) / D;
#pragma unroll
        for (int t = 0; t < TASKS; t++) {
            int e = tid + t * NT;
            int rl = e & 127, o = e >> 7;
            int r = m * 128 + rl;
            int b = r / D, bl = b - b_lo, i = r - b * D;
            const float* s = stgF + bl * STRIDE + (o * 8) * D + i;
            float v[8];
#pragma unroll
            for (int j = 0; j < 8; j++) v[j] = s[j * D];
            uint32_t p0 = packh2(v[0], v[1]), p1 = packh2(v[2], v[3]);
            uint32_t p2 = packh2(v[4], v[5]), p3 = packh2(v[6], v[7]);
            *(uint4*)(smem + A_OFF + sw128((uint32_t)(rl * 128 + o * 16))) =
                make_uint4(p0, p1, p2, p3);
        }
    };

    // D==1: coalesced LDG float4 -> regs
    auto ldg_chunk = [&](int m, int c) {
#pragma unroll
        for (int t = 0; t < TASKS; t++) {
            int e = tid + t * NT;
            int rl = e & 127, o = e >> 7;
            const float* xp = x + (size_t)(m * 128 + rl) * FEAT + xo + c * KC + o * 8;
            float4 q0 = *(const float4*)xp;
            float4 q1 = *(const float4*)(xp + 4);
            st[t][0] = q0.x; st[t][1] = q0.y; st[t][2] = q0.z; st[t][3] = q0.w;
            st[t][4] = q1.x; st[t][5] = q1.y; st[t][6] = q1.z; st[t][7] = q1.w;
        }
    };
    auto sts_chunk = [&](int buf) {
#pragma unroll
        for (int t = 0; t < TASKS; t++) {
            int e = tid + t * NT;
            int rl = e & 127, o = e >> 7;
            uint32_t p0 = packh2(st[t][0], st[t][1]), p1 = packh2(st[t][2], st[t][3]);
            uint32_t p2 = packh2(st[t][4], st[t][5]), p3 = packh2(st[t][6], st[t][7]);
            *(uint4*)(smem + A_OFF + buf * 16384 +
                      sw128((uint32_t)(rl * 128 + o * 16))) = make_uint4(p0, p1, p2, p3);
        }
    };

    // 2-pass MMA: A * Whi + A * Wlo
    auto mma_chunk = [&](uint32_t aoff, int c) {
        const int q = lane >> 3, p = lane & 7;
#pragma unroll
        for (int s = 0; s < KSTEPS; s++) {
            uint32_t af[2][4];
#pragma unroll
            for (int mt = 0; mt < 2; mt++) {
                uint32_t row = (uint32_t)(wm * 32 + mt * 16 + (q & 1) * 8 + p);
                uint32_t kb  = (uint32_t)(s * 32 + (q >> 1) * 16);
                ldsm4(af[mt], sb + aoff + sw128(row * 128 + kb));
            }
#pragma unroll
            for (int ntp = 0; ntp < NT8 / 2; ntp++) {
                uint32_t vv = (uint32_t)(wn * WN + ntp * 16 + (q >> 1) * 8 + p);
                uint32_t kb = (uint32_t)(s * 32 + (q & 1) * 16);
                uint32_t off = (uint32_t)(c * (BN * 128)) + sw128(vv * 128 + kb);
                uint32_t bh[4], bl4[4];
                ldsm4(bh,  sb + off);
                ldsm4(bl4, sb + WSZ + off);
#pragma unroll
                for (int t2 = 0; t2 < 2; t2++) {
#pragma unroll
                    for (int mt = 0; mt < 2; mt++) {
                        mma16816(acc[mt][ntp * 2 + t2], af[mt], bh + 2 * t2);
                        mma16816(acc[mt][ntp * 2 + t2], af[mt], bl4 + 2 * t2);
                    }
                }
            }
        }
    };

    auto epilogue = [&](int m) {
        const int row_base = m * 128 + wm * 32 + (lane >> 2);
        const int col_base = v0 + wn * WN + 2 * (lane & 3);
#pragma unroll
        for (int mt = 0; mt < 2; mt++) {
#pragma unroll
            for (int nt = 0; nt < NT8; nt++) {
                float* a = acc[mt][nt];
                int cc = col_base + nt * 8;
                int r1 = row_base + mt * 16, r2 = r1 + 8;
                if (D == 1) {
                    *(float2*)(out + (size_t)r1 * FEAT + xo + cc) =
                        make_float2(a[0], a[1]);
                    *(float2*)(out + (size_t)r2 * FEAT + xo + cc) =
                        make_float2(a[2], a[3]);
                } else {
                    int b1 = r1 / D, i1 = r1 - b1 * D;
                    int b2 = r2 / D, i2 = r2 - b2 * D;
                    float* o1 = out + (size_t)b1 * FEAT + xo + i1;
                    float* o2 = out + (size_t)b2 * FEAT + xo + i2;
                    o1[(size_t)cc * D]       = a[0];
                    o1[(size_t)(cc + 1) * D] = a[1];
                    o2[(size_t)cc * D]       = a[2];
                    o2[(size_t)(cc + 1) * D] = a[3];
                }
            }
        }
    };

    if (D == 1) {
        ldg_chunk(blockIdx.x, 0);
        __syncthreads();                       // W tiles visible
        int g = 0;
        for (int m = blockIdx.x; m < mtiles; m += gridDim.x) {
#pragma unroll
            for (int mt = 0; mt < 2; mt++)
#pragma unroll
                for (int nt = 0; nt < NT8; nt++)
#pragma unroll
                    for (int j = 0; j < 4; j++) acc[mt][nt][j] = 0.0f;
#pragma unroll 1
            for (int c = 0; c < NCH; c++) {
                int buf = g & 1;
                sts_chunk(buf);
                __syncthreads();
                int cn = c + 1, mn = m;
                if (cn == NCH) { cn = 0; mn = m + gridDim.x; }
                if (mn < mtiles) ldg_chunk(mn, cn);
                mma_chunk((uint32_t)(A_OFF + buf * 16384), c);
                g++;
            }
            epilogue(m);
        }
    } else {
        stage_ld(blockIdx.x, 0);
        for (int m = blockIdx.x; m < mtiles; m += gridDim.x) {
#pragma unroll
            for (int mt = 0; mt < 2; mt++)
#pragma unroll
                for (int nt = 0; nt < NT8; nt++)
#pragma unroll
                    for (int j = 0; j < 4; j++) acc[mt][nt][j] = 0.0f;
#pragma unroll 1
            for (int c = 0; c < NCH; c++) {
                asm volatile("cp.async.wait_group 0;" ::: "memory");
                __syncthreads();               // staging ready (+ W on 1st iter)
                conv_chunk(m);
                __syncthreads();               // A ready; staging free
                int cn = c + 1, mn = m;
                if (cn == NCH) { cn = 0; mn = m + gridDim.x; }
                if (mn < mtiles) stage_ld(mn, cn);   // overlaps MMA
                mma_chunk((uint32_t)A_OFF, c);
            }
            epilogue(m);
        }
    }
}

extern "C" void kernel_launch(void* const* d_in, const int* in_sizes, int n_in,
                              void* d_out, int out_size)
{
    const float* x = (const float*)d_in[0];
    const float* w = (const float*)d_in[1];
    float* out = (float*)d_out;

    prep_w<<<(87040 + 255) / 256, 256>>>(w);

    // smem budgets (must mirror template math)
    constexpr int SM0 = 2 * 65536 + 2 * 16384;                 // 163840
    constexpr int SM1 = 2 * 32768 + 16384 + 44 * 196 * 4;      // 116416
    constexpr int SM2 = 2 * 8192  + 16384 + 27 * 324 * 4;      // 67760
    constexpr int SM3 = 2 * 4096  + 16384 + 20 * 228 * 4;      // 42816

    cudaFuncSetAttribute(eqlin<256, 1, 128, 512>, cudaFuncAttributeMaxDynamicSharedMemorySize, SM0);
    cudaFuncSetAttribute(eqlin<128, 3, 128, 512>, cudaFuncAttributeMaxDynamicSharedMemorySize, SM1);
    cudaFuncSetAttribute(eqlin<64, 5, 64, 256>,   cudaFuncAttributeMaxDynamicSharedMemorySize, SM2);
    cudaFuncSetAttribute(eqlin<32, 7, 32, 256>,   cudaFuncAttributeMaxDynamicSharedMemorySize, SM3);

    // block 0: mul=256, d=1: 1024 m-tiles, 2 n-tiles of 128
    eqlin<256, 1, 128, 512><<<dim3(74, 2), 512, SM0>>>(x, out, 0, 0, 1024);
    // block 1: mul=128, d=3: 3072 m-tiles
    eqlin<128, 3, 128, 512><<<dim3(148, 1), 512, SM1>>>(x, out, 256, 65536, 3072);
    // block 2: mul=64, d=5: 5120 m-tiles (2 CTAs/SM)
    eqlin<64, 5, 64, 256><<<dim3(296, 1), 256, SM2>>>(x, out, 640, 81920, 5120);
    // block 3: mul=32, d=7: 7168 m-tiles (2 CTAs/SM)
    eqlin<32, 7, 32, 256><<<dim3(296, 1), 256, SM3>>>(x, out, 960, 86016, 7168);
}

// round 6
// speedup vs baseline: 5.1626x; 1.8371x over previous
#include <cuda_runtime.h>
#include <cuda_fp16.h>
#include <cstdint>

#define FEAT 1184
#define BATCH 131072

// Pre-scaled fp16 weights: fp16(c*W)
__device__ __align__(16) __half g_wh[87040];

__global__ void prep_w(const float* __restrict__ w) {
    int i = blockIdx.x * 256 + threadIdx.x;
    if (i >= 87040) return;
    float c = (i < 65536) ? 0.0625f
            : (i < 81920) ? 0.08838834764831843f
            : (i < 86016) ? 0.125f
            : 0.17677669529663687f;
    g_wh[i] = __float2half_rn(w[i] * c);
}

static __device__ __forceinline__ uint32_t s2u(const void* p) {
    return (uint32_t)__cvta_generic_to_shared(p);
}
static __device__ __forceinline__ uint32_t sw128(uint32_t off) {
    return off ^ ((off >> 3) & 0x70);
}
static __device__ __forceinline__ uint32_t packh2(float a, float b) {
    __half2 h = __floats2half2_rn(a, b);
    return *(uint32_t*)&h;
}
static __device__ __forceinline__ void ldsm4(uint32_t* r, uint32_t addr) {
    asm volatile("ldmatrix.sync.aligned.m8n8.x4.shared.b16 {%0,%1,%2,%3}, [%4];"
                 : "=r"(r[0]), "=r"(r[1]), "=r"(r[2]), "=r"(r[3]) : "r"(addr));
}
static __device__ __forceinline__ void mma16816(float* c, const uint32_t* a,
                                                const uint32_t* b) {
    asm volatile("mma.sync.aligned.m16n8k16.row.col.f32.f16.f16.f32 "
                 "{%0,%1,%2,%3}, {%4,%5,%6,%7}, {%8,%9}, {%0,%1,%2,%3};"
                 : "+f"(c[0]), "+f"(c[1]), "+f"(c[2]), "+f"(c[3])
                 : "r"(a[0]), "r"(a[1]), "r"(a[2]), "r"(a[3]),
                   "r"(b[0]), "r"(b[1]));
}

// y[r, v] = sum_k A[r,k] * fp16(c*W[v,k]),  r = b*D + i,
//   A[r,k] = x[b*FEAT + xo + k*D + i]
template<int MUL, int D, int BN, int NT, int WNW>
__global__ void __launch_bounds__(NT, (NT == 256) ? 2 : 1) eqlin(
    const float* __restrict__ x, float* __restrict__ out,
    int xo, int wo, int mtiles)
{
    constexpr int KC      = (MUL < 64) ? MUL : 64;
    constexpr int NCH     = MUL / KC;
    constexpr int KSTEPS  = KC / 16;
    constexpr int OCTS    = KC / 8;
    constexpr int WSZ     = NCH * BN * 128;      // W bytes (single fp16)
    constexpr int A_OFF   = WSZ;
    constexpr int NABUF   = (D == 1) ? 2 : 1;
    constexpr int STG_OFF = A_OFF + NABUF * 16384;
    constexpr int NB      = 127 / D + 2;         // batches touched per tile
    constexpr int STRIDE  = KC * D + 4;          // floats; == 4 (mod 32)
    constexpr int F4PB    = KC * D / 4;          // float4 per batch per chunk
    constexpr int WARPS   = NT / 32;
    constexpr int WN      = BN / WNW;            // == 32 in all configs
    constexpr int NT8     = WN / 8;
    constexpr int MWARPS  = WARPS / WNW;
    constexpr int MT      = 128 / MWARPS / 16;   // m16 frags per warp
    constexpr int TASKS   = (128 * OCTS) / NT;

    extern __shared__ char smem[];
    const uint32_t sb = s2u(smem);
    float* stgF = (float*)(smem + STG_OFF);
    const int tid  = threadIdx.x;
    const int lane = tid & 31;
    const int warp = tid >> 5;
    const int wm   = warp / WNW;
    const int wn   = warp % WNW;

    // ---- Resident W (fp16), chunk-major 128B rows, SW128 ----
    for (int e = tid; e < BN * (MUL / 8); e += NT) {
        int v = e / (MUL / 8), o = e % (MUL / 8);
        int k = o * 8;
        uint4 hv = *(const uint4*)(g_wh + wo + (size_t)v * MUL + k);
        uint32_t off = (uint32_t)((k / KC) * (BN * 128) + v * 128 + (k % KC) * 2);
        *(uint4*)(smem + sw128(off)) = hv;
    }

    float acc[MT][NT8][4];
    float st[(D == 1) ? TASKS : 1][8];

    // cp.async staging: contiguous float4 span of the chunk
    auto stage_ld = [&](int m, int c) {
        int b_lo = (m * 128) / D;
        for (int e = tid; e < NB * F4PB; e += NT) {
            int bl = e / F4PB, f = e - bl * F4PB;
            int b = b_lo + bl;
            if (b >= BATCH) b = BATCH - 1;
            const float* src = x + (size_t)b * FEAT + xo + c * (KC * D) + f * 4;
            uint32_t dst = sb + STG_OFF + (uint32_t)(bl * STRIDE + f * 4) * 4;
            asm volatile("cp.async.cg.shared.global [%0], [%1], 16;"
                         :: "r"(dst), "l"(src) : "memory");
        }
        asm volatile("cp.async.commit_group;" ::: "memory");
    };

    // D>1: strided LDS from staging -> fp16 -> swizzled A
    auto conv_chunk = [&](int m) {
        int b_lo = (m * 128) / D;
#pragma unroll
        for (int t = 0; t < TASKS; t++) {
            int e = tid + t * NT;
            int rl = e & 127, o = e >> 7;
            int r = m * 128 + rl;
            int b = r / D, bl = b - b_lo, i = r - b * D;
            const float* s = stgF + bl * STRIDE + (o * 8) * D + i;
            float v[8];
#pragma unroll
            for (int j = 0; j < 8; j++) v[j] = s[j * D];
            uint32_t p0 = packh2(v[0], v[1]), p1 = packh2(v[2], v[3]);
            uint32_t p2 = packh2(v[4], v[5]), p3 = packh2(v[6], v[7]);
            *(uint4*)(smem + A_OFF + sw128((uint32_t)(rl * 128 + o * 16))) =
                make_uint4(p0, p1, p2, p3);
        }
    };

    // D==1: coalesced LDG float4 -> regs -> swizzled A
    auto ldg_chunk = [&](int m, int c) {
#pragma unroll
        for (int t = 0; t < TASKS; t++) {
            int e = tid + t * NT;
            int rl = e & 127, o = e >> 7;
            const float* xp = x + (size_t)(m * 128 + rl) * FEAT + xo + c * KC + o * 8;
            float4 q0 = *(const float4*)xp;
            float4 q1 = *(const float4*)(xp + 4);
            st[t][0] = q0.x; st[t][1] = q0.y; st[t][2] = q0.z; st[t][3] = q0.w;
            st[t][4] = q1.x; st[t][5] = q1.y; st[t][6] = q1.z; st[t][7] = q1.w;
        }
    };
    auto sts_chunk = [&](int buf) {
#pragma unroll
        for (int t = 0; t < TASKS; t++) {
            int e = tid + t * NT;
            int rl = e & 127, o = e >> 7;
            uint32_t p0 = packh2(st[t][0], st[t][1]), p1 = packh2(st[t][2], st[t][3]);
            uint32_t p2 = packh2(st[t][4], st[t][5]), p3 = packh2(st[t][6], st[t][7]);
            *(uint4*)(smem + A_OFF + buf * 16384 +
                      sw128((uint32_t)(rl * 128 + o * 16))) = make_uint4(p0, p1, p2, p3);
        }
    };

    auto mma_chunk = [&](uint32_t aoff, int c) {
        const int q = lane >> 3, p = lane & 7;
#pragma unroll
        for (int s = 0; s < KSTEPS; s++) {
            uint32_t af[MT][4];
#pragma unroll
            for (int mt = 0; mt < MT; mt++) {
                uint32_t row = (uint32_t)(wm * (MT * 16) + mt * 16 + (q & 1) * 8 + p);
                uint32_t kb  = (uint32_t)(s * 32 + (q >> 1) * 16);
                ldsm4(af[mt], sb + aoff + sw128(row * 128 + kb));
            }
#pragma unroll
            for (int ntp = 0; ntp < NT8 / 2; ntp++) {
                uint32_t vv = (uint32_t)(wn * WN + ntp * 16 + (q >> 1) * 8 + p);
                uint32_t kb = (uint32_t)(s * 32 + (q & 1) * 16);
                uint32_t bh[4];
                ldsm4(bh, sb + (uint32_t)(c * (BN * 128)) + sw128(vv * 128 + kb));
#pragma unroll
                for (int t2 = 0; t2 < 2; t2++)
#pragma unroll
                    for (int mt = 0; mt < MT; mt++)
                        mma16816(acc[mt][ntp * 2 + t2], af[mt], bh + 2 * t2);
            }
        }
    };

    auto epilogue = [&](int m) {
        const int row_base = m * 128 + wm * (MT * 16) + (lane >> 2);
        const int col_base = wn * WN + 2 * (lane & 3);
#pragma unroll
        for (int mt = 0; mt < MT; mt++) {
#pragma unroll
            for (int nt = 0; nt < NT8; nt++) {
                float* a = acc[mt][nt];
                int cc = col_base + nt * 8;
                int r1 = row_base + mt * 16, r2 = r1 + 8;
                if (D == 1) {
                    *(float2*)(out + (size_t)r1 * FEAT + xo + cc) =
                        make_float2(a[0], a[1]);
                    *(float2*)(out + (size_t)r2 * FEAT + xo + cc) =
                        make_float2(a[2], a[3]);
                } else {
                    int b1 = r1 / D, i1 = r1 - b1 * D;
                    int b2 = r2 / D, i2 = r2 - b2 * D;
                    float* o1 = out + (size_t)b1 * FEAT + xo + i1;
                    float* o2 = out + (size_t)b2 * FEAT + xo + i2;
                    o1[(size_t)cc * D]       = a[0];
                    o1[(size_t)(cc + 1) * D] = a[1];
                    o2[(size_t)cc * D]       = a[2];
                    o2[(size_t)(cc + 1) * D] = a[3];
                }
            }
        }
    };

    if (D == 1) {
        ldg_chunk(blockIdx.x, 0);
        __syncthreads();                       // W visible
        int g = 0;
        for (int m = blockIdx.x; m < mtiles; m += gridDim.x) {
#pragma unroll
            for (int mt = 0; mt < MT; mt++)
#pragma unroll
                for (int nt = 0; nt < NT8; nt++)
#pragma unroll
                    for (int j = 0; j < 4; j++) acc[mt][nt][j] = 0.0f;
#pragma unroll 1
            for (int c = 0; c < NCH; c++) {
                int buf = g & 1;
                sts_chunk(buf);
                __syncthreads();
                int cn = c + 1, mn = m;
                if (cn == NCH) { cn = 0; mn = m + gridDim.x; }
                if (mn < mtiles) ldg_chunk(mn, cn);
                mma_chunk((uint32_t)(A_OFF + buf * 16384), c);
                g++;
            }
            epilogue(m);
        }
    } else {
        stage_ld(blockIdx.x, 0);
        for (int m = blockIdx.x; m < mtiles; m += gridDim.x) {
#pragma unroll
            for (int mt = 0; mt < MT; mt++)
#pragma unroll
                for (int nt = 0; nt < NT8; nt++)
#pragma unroll
                    for (int j = 0; j < 4; j++) acc[mt][nt][j] = 0.0f;
#pragma unroll 1
            for (int c = 0; c < NCH; c++) {
                asm volatile("cp.async.wait_group 0;" ::: "memory");
                __syncthreads();               // staging (+W first iter) ready
                conv_chunk(m);
                __syncthreads();               // A ready; staging free
                int cn = c + 1, mn = m;
                if (cn == NCH) { cn = 0; mn = m + gridDim.x; }
                if (mn < mtiles) stage_ld(mn, cn);   // overlaps MMA
                mma_chunk((uint32_t)A_OFF, c);
            }
            epilogue(m);
        }
    }
}

extern "C" void kernel_launch(void* const* d_in, const int* in_sizes, int n_in,
                              void* d_out, int out_size)
{
    const float* x = (const float*)d_in[0];
    const float* w = (const float*)d_in[1];
    float* out = (float*)d_out;

    prep_w<<<(87040 + 255) / 256, 256>>>(w);

    // smem budgets (mirror template math)
    constexpr int SM0 = 4 * 256 * 128 + 2 * 16384;             // 163840
    constexpr int SM1 = 2 * 128 * 128 + 16384 + 44 * 196 * 4;  // 83648
    constexpr int SM2 = 64 * 128 + 16384 + 27 * 324 * 4;       // 59568
    constexpr int SM3 = 32 * 128 + 16384 + 20 * 228 * 4;       // 38720

    cudaFuncSetAttribute(eqlin<256, 1, 256, 512, 8>, cudaFuncAttributeMaxDynamicSharedMemorySize, SM0);
    cudaFuncSetAttribute(eqlin<128, 3, 128, 512, 4>, cudaFuncAttributeMaxDynamicSharedMemorySize, SM1);
    cudaFuncSetAttribute(eqlin<64, 5, 64, 256, 2>,   cudaFuncAttributeMaxDynamicSharedMemorySize, SM2);
    cudaFuncSetAttribute(eqlin<32, 7, 32, 256, 1>,   cudaFuncAttributeMaxDynamicSharedMemorySize, SM3);

    // block 0: mul=256, d=1: 1024 m-tiles, full N=256 in one CTA
    eqlin<256, 1, 256, 512, 8><<<148, 512, SM0>>>(x, out, 0, 0, 1024);
    // block 1: mul=128, d=3: 3072 m-tiles
    eqlin<128, 3, 128, 512, 4><<<148, 512, SM1>>>(x, out, 256, 65536, 3072);
    // block 2: mul=64, d=5: 5120 m-tiles (2 CTAs/SM)
    eqlin<64, 5, 64, 256, 2><<<296, 256, SM2>>>(x, out, 640, 81920, 5120);
    // block 3: mul=32, d=7: 7168 m-tiles (2 CTAs/SM)
    eqlin<32, 7, 32, 256, 1><<<296, 256, SM3>>>(x, out, 960, 86016, 7168);
}